// round 3
// baseline (speedup 1.0000x reference)
#include <cuda_runtime.h>
#include <stdint.h>

// Fixed problem shape (from reference): N=700000 nodes, H=64 feature width.
#define NMAX 700000
#define HW 64

// Scratch (allocation-free rule: __device__ globals, ~361MB .bss).
__device__ float g_deg[NMAX];
__device__ float g_dinv[NMAX];
__device__ float g_h[(size_t)NMAX * HW];    // h1, then h2
__device__ float g_agg[(size_t)NMAX * HW];  // aggregation accumulator (re-init every call)

// ---------------------------------------------------------------------------
__global__ void k_init_deg(int n) {
    int i = blockIdx.x * blockDim.x + threadIdx.x;
    if (i < n) g_deg[i] = 1.0f;  // self-loop
}

__global__ void k_count_deg(const int* __restrict__ dst, int E) {
    int e = blockIdx.x * blockDim.x + threadIdx.x;
    if (e < E) atomicAdd(&g_deg[dst[e]], 1.0f);
}

__global__ void k_dinv(int n) {
    int i = blockIdx.x * blockDim.x + threadIdx.x;
    if (i < n) g_dinv[i] = rsqrtf(g_deg[i]);
}

// h = x @ W1 ; agg = h * dinv^2 (self-loop init). One warp per row.
__global__ void k_gemm1(const float* __restrict__ x, const float* __restrict__ W1, int n) {
    __shared__ float Ws[32 * 64];
    for (int i = threadIdx.x; i < 32 * 64; i += blockDim.x) Ws[i] = W1[i];
    __syncthreads();
    int warp = threadIdx.x >> 5, lane = threadIdx.x & 31;
    int r = blockIdx.x * 8 + warp;
    if (r >= n) return;
    float xv = x[(size_t)r * 32 + lane];
    float a0 = 0.f, a1 = 0.f;
#pragma unroll
    for (int k = 0; k < 32; k++) {
        float xk = __shfl_sync(0xffffffffu, xv, k);
        a0 = fmaf(xk, Ws[k * 64 + lane], a0);
        a1 = fmaf(xk, Ws[k * 64 + lane + 32], a1);
    }
    size_t base = (size_t)r * 64;
    float di = g_dinv[r], d2 = di * di;
    g_h[base + lane] = a0;
    g_h[base + lane + 32] = a1;
    g_agg[base + lane] = a0 * d2;
    g_agg[base + lane + 32] = a1 * d2;
}

// Edge scatter: agg[dst] += h[src] * dinv[src]*dinv[dst]. One warp per edge,
// each lane owns 2 contiguous floats (float2 gather, 2 RED.ADD.F32).
__global__ void k_edge(const int* __restrict__ src,
                       const int* __restrict__ dst, int E) {
    int e = blockIdx.x * 8 + (threadIdx.x >> 5);
    if (e >= E) return;
    int lane = threadIdx.x & 31;
    int s = src[e], d = dst[e];                // uniform per warp -> broadcast
    float coef = g_dinv[s] * g_dinv[d];
    const float2 v = *(const float2*)(g_h + (size_t)s * 64 + lane * 2);
    float* ap = g_agg + (size_t)d * 64 + lane * 2;
    atomicAdd(ap, v.x * coef);
    atomicAdd(ap + 1, v.y * coef);
}

// h2 = relu(agg + b1) @ W2 ; agg re-init (in-place, row-local) = h2 * dinv^2.
__global__ void k_gemm2(const float* __restrict__ W2, const float* __restrict__ b1, int n) {
    __shared__ float Ws[64 * 64];
    __shared__ float rowbuf[8][64];
    for (int i = threadIdx.x; i < 64 * 64; i += blockDim.x) Ws[i] = W2[i];
    __syncthreads();
    int warp = threadIdx.x >> 5, lane = threadIdx.x & 31;
    int r = blockIdx.x * 8 + warp;
    if (r >= n) return;
    size_t base = (size_t)r * 64;
    float2 av = *(const float2*)(g_agg + base + (size_t)lane * 2);
    rowbuf[warp][lane * 2]     = fmaxf(av.x + b1[lane * 2], 0.f);
    rowbuf[warp][lane * 2 + 1] = fmaxf(av.y + b1[lane * 2 + 1], 0.f);
    __syncwarp();
    float a0 = 0.f, a1 = 0.f;
#pragma unroll
    for (int k = 0; k < 64; k++) {
        float ak = rowbuf[warp][k];
        a0 = fmaf(ak, Ws[k * 64 + lane], a0);
        a1 = fmaf(ak, Ws[k * 64 + lane + 32], a1);
    }
    float di = g_dinv[r], d2 = di * di;
    g_h[base + lane] = a0;
    g_h[base + lane + 32] = a1;
    g_agg[base + lane] = a0 * d2;
    g_agg[base + lane + 32] = a1 * d2;
}

// out[g] = relu(agg[g,:] + b2_bcast) . Wfc + bfc.  One warp per graph (896 elems).
__global__ void k_final(const float* __restrict__ b2, const float* __restrict__ Wfc,
                        const float* __restrict__ bfc, float* __restrict__ out, int B) {
    __shared__ float Ws[896];
    __shared__ float bs[64];
    for (int i = threadIdx.x; i < 896; i += blockDim.x) Ws[i] = Wfc[i];
    if (threadIdx.x < 64) bs[threadIdx.x] = b2[threadIdx.x];
    __syncthreads();
    int warp = threadIdx.x >> 5, lane = threadIdx.x & 31;
    int g = blockIdx.x * 8 + warp;
    if (g >= B) return;
    const float* row = g_agg + (size_t)g * 896;
    float acc = 0.f;
#pragma unroll
    for (int j = 0; j < 7; j++) {
        int idx = (j * 32 + lane) * 4;
        float4 v = *(const float4*)(row + idx);
        acc = fmaf(fmaxf(v.x + bs[idx & 63], 0.f), Ws[idx], acc);
        acc = fmaf(fmaxf(v.y + bs[(idx + 1) & 63], 0.f), Ws[idx + 1], acc);
        acc = fmaf(fmaxf(v.z + bs[(idx + 2) & 63], 0.f), Ws[idx + 2], acc);
        acc = fmaf(fmaxf(v.w + bs[(idx + 3) & 63], 0.f), Ws[idx + 3], acc);
    }
#pragma unroll
    for (int o = 16; o; o >>= 1) acc += __shfl_down_sync(0xffffffffu, acc, o);
    if (lane == 0) out[g] = acc + bfc[0];
}

// ---------------------------------------------------------------------------
extern "C" void kernel_launch(void* const* d_in, const int* in_sizes, int n_in,
                              void* d_out, int out_size) {
    const float* x    = (const float*)d_in[0];
    const int*   edges = (const int*)d_in[1];   // int32: JAX x64 disabled downcasts int64
    const float* W1   = (const float*)d_in[2];
    const float* b1   = (const float*)d_in[3];
    const float* W2   = (const float*)d_in[4];
    const float* b2   = (const float*)d_in[5];
    const float* Wfc  = (const float*)d_in[6];
    const float* bfc  = (const float*)d_in[7];
    float* out = (float*)d_out;

    int n = in_sizes[0] / 32;   // 700000
    int E = in_sizes[1] / 2;    // 4000000
    int B = n / 14;             // 50000
    const int* src = edges;
    const int* dst = edges + E;

    k_init_deg<<<(n + 255) / 256, 256>>>(n);
    k_count_deg<<<(E + 255) / 256, 256>>>(dst, E);
    k_dinv<<<(n + 255) / 256, 256>>>(n);

    // Layer 1
    k_gemm1<<<(n + 7) / 8, 256>>>(x, W1, n);
    k_edge<<<(E + 7) / 8, 256>>>(src, dst, E);

    // Layer 2 (fused relu+bias+GEMM+self-loop re-init)
    k_gemm2<<<(n + 7) / 8, 256>>>(W2, b1, n);
    k_edge<<<(E + 7) / 8, 256>>>(src, dst, E);

    // FC head
    k_final<<<(B + 7) / 8, 256>>>(b2, Wfc, bfc, out, B);
}

// round 4
// speedup vs baseline: 1.0011x; 1.0011x over previous
#include <cuda_runtime.h>
#include <stdint.h>

// Fixed problem shape (from reference): N=700000 nodes, H=64 feature width.
#define NMAX 700000
#define HW 64

// Scratch (allocation-free rule: __device__ globals, ~361MB .bss).
__device__ float g_deg[NMAX];
__device__ float g_dinv[NMAX];
__device__ float g_h[(size_t)NMAX * HW];    // h1, then h2
__device__ float g_agg[(size_t)NMAX * HW];  // aggregation accumulator (re-init every call)

// ---------------------------------------------------------------------------
__global__ void k_init_deg(int n) {
    int i = blockIdx.x * blockDim.x + threadIdx.x;
    if (i < n) g_deg[i] = 1.0f;  // self-loop
}

__global__ void k_count_deg(const int* __restrict__ dst, int E) {
    int e = blockIdx.x * blockDim.x + threadIdx.x;
    if (e < E) atomicAdd(&g_deg[dst[e]], 1.0f);
}

__global__ void k_dinv(int n) {
    int i = blockIdx.x * blockDim.x + threadIdx.x;
    if (i < n) g_dinv[i] = rsqrtf(g_deg[i]);
}

// h = x @ W1 ; agg = h * dinv^2 (self-loop init). One warp per row.
__global__ void k_gemm1(const float* __restrict__ x, const float* __restrict__ W1, int n) {
    __shared__ float Ws[32 * 64];
    for (int i = threadIdx.x; i < 32 * 64; i += blockDim.x) Ws[i] = W1[i];
    __syncthreads();
    int warp = threadIdx.x >> 5, lane = threadIdx.x & 31;
    int r = blockIdx.x * 8 + warp;
    if (r >= n) return;
    float xv = x[(size_t)r * 32 + lane];
    float a0 = 0.f, a1 = 0.f;
#pragma unroll
    for (int k = 0; k < 32; k++) {
        float xk = __shfl_sync(0xffffffffu, xv, k);
        a0 = fmaf(xk, Ws[k * 64 + lane], a0);
        a1 = fmaf(xk, Ws[k * 64 + lane + 32], a1);
    }
    size_t base = (size_t)r * 64;
    float di = g_dinv[r], d2 = di * di;
    g_h[base + lane] = a0;
    g_h[base + lane + 32] = a1;
    g_agg[base + lane] = a0 * d2;
    g_agg[base + lane + 32] = a1 * d2;
}

// Edge scatter: agg[dst] += h[src] * dinv[src]*dinv[dst]. One warp per edge,
// each lane owns 2 contiguous floats (float2 gather, 2 RED.ADD.F32).
__global__ void k_edge(const int* __restrict__ src,
                       const int* __restrict__ dst, int E) {
    int e = blockIdx.x * 8 + (threadIdx.x >> 5);
    if (e >= E) return;
    int lane = threadIdx.x & 31;
    int s = src[e], d = dst[e];                // uniform per warp -> broadcast
    float coef = g_dinv[s] * g_dinv[d];
    const float2 v = *(const float2*)(g_h + (size_t)s * 64 + lane * 2);
    float* ap = g_agg + (size_t)d * 64 + lane * 2;
    atomicAdd(ap, v.x * coef);
    atomicAdd(ap + 1, v.y * coef);
}

// h2 = relu(agg + b1) @ W2 ; agg re-init (in-place, row-local) = h2 * dinv^2.
__global__ void k_gemm2(const float* __restrict__ W2, const float* __restrict__ b1, int n) {
    __shared__ float Ws[64 * 64];
    __shared__ float rowbuf[8][64];
    for (int i = threadIdx.x; i < 64 * 64; i += blockDim.x) Ws[i] = W2[i];
    __syncthreads();
    int warp = threadIdx.x >> 5, lane = threadIdx.x & 31;
    int r = blockIdx.x * 8 + warp;
    if (r >= n) return;
    size_t base = (size_t)r * 64;
    float2 av = *(const float2*)(g_agg + base + (size_t)lane * 2);
    rowbuf[warp][lane * 2]     = fmaxf(av.x + b1[lane * 2], 0.f);
    rowbuf[warp][lane * 2 + 1] = fmaxf(av.y + b1[lane * 2 + 1], 0.f);
    __syncwarp();
    float a0 = 0.f, a1 = 0.f;
#pragma unroll
    for (int k = 0; k < 64; k++) {
        float ak = rowbuf[warp][k];
        a0 = fmaf(ak, Ws[k * 64 + lane], a0);
        a1 = fmaf(ak, Ws[k * 64 + lane + 32], a1);
    }
    float di = g_dinv[r], d2 = di * di;
    g_h[base + lane] = a0;
    g_h[base + lane + 32] = a1;
    g_agg[base + lane] = a0 * d2;
    g_agg[base + lane + 32] = a1 * d2;
}

// out[g] = relu(agg[g,:] + b2_bcast) . Wfc + bfc.  One warp per graph (896 elems).
__global__ void k_final(const float* __restrict__ b2, const float* __restrict__ Wfc,
                        const float* __restrict__ bfc, float* __restrict__ out, int B) {
    __shared__ float Ws[896];
    __shared__ float bs[64];
    for (int i = threadIdx.x; i < 896; i += blockDim.x) Ws[i] = Wfc[i];
    if (threadIdx.x < 64) bs[threadIdx.x] = b2[threadIdx.x];
    __syncthreads();
    int warp = threadIdx.x >> 5, lane = threadIdx.x & 31;
    int g = blockIdx.x * 8 + warp;
    if (g >= B) return;
    const float* row = g_agg + (size_t)g * 896;
    float acc = 0.f;
#pragma unroll
    for (int j = 0; j < 7; j++) {
        int idx = (j * 32 + lane) * 4;
        float4 v = *(const float4*)(row + idx);
        acc = fmaf(fmaxf(v.x + bs[idx & 63], 0.f), Ws[idx], acc);
        acc = fmaf(fmaxf(v.y + bs[(idx + 1) & 63], 0.f), Ws[idx + 1], acc);
        acc = fmaf(fmaxf(v.z + bs[(idx + 2) & 63], 0.f), Ws[idx + 2], acc);
        acc = fmaf(fmaxf(v.w + bs[(idx + 3) & 63], 0.f), Ws[idx + 3], acc);
    }
#pragma unroll
    for (int o = 16; o; o >>= 1) acc += __shfl_down_sync(0xffffffffu, acc, o);
    if (lane == 0) out[g] = acc + bfc[0];
}

// ---------------------------------------------------------------------------
extern "C" void kernel_launch(void* const* d_in, const int* in_sizes, int n_in,
                              void* d_out, int out_size) {
    const float* x    = (const float*)d_in[0];
    const int*   edges = (const int*)d_in[1];   // int32: JAX x64 disabled downcasts int64
    const float* W1   = (const float*)d_in[2];
    const float* b1   = (const float*)d_in[3];
    const float* W2   = (const float*)d_in[4];
    const float* b2   = (const float*)d_in[5];
    const float* Wfc  = (const float*)d_in[6];
    const float* bfc  = (const float*)d_in[7];
    float* out = (float*)d_out;

    int n = in_sizes[0] / 32;   // 700000
    int E = in_sizes[1] / 2;    // 4000000
    int B = n / 14;             // 50000
    const int* src = edges;
    const int* dst = edges + E;

    k_init_deg<<<(n + 255) / 256, 256>>>(n);
    k_count_deg<<<(E + 255) / 256, 256>>>(dst, E);
    k_dinv<<<(n + 255) / 256, 256>>>(n);

    // Layer 1
    k_gemm1<<<(n + 7) / 8, 256>>>(x, W1, n);
    k_edge<<<(E + 7) / 8, 256>>>(src, dst, E);

    // Layer 2 (fused relu+bias+GEMM+self-loop re-init)
    k_gemm2<<<(n + 7) / 8, 256>>>(W2, b1, n);
    k_edge<<<(E + 7) / 8, 256>>>(src, dst, E);

    // FC head
    k_final<<<(B + 7) / 8, 256>>>(b2, Wfc, bfc, out, B);
}

// round 5
// speedup vs baseline: 1.0014x; 1.0003x over previous
#include <cuda_runtime.h>
#include <stdint.h>

// Fixed problem shape (from reference): N=700000 nodes, H=64 feature width.
#define NMAX 700000
#define HW 64

// Scratch (allocation-free rule: __device__ globals, ~361MB .bss).
__device__ float g_deg[NMAX];
__device__ float g_dinv[NMAX];
__device__ float g_h[(size_t)NMAX * HW];    // h1, then h2
__device__ float g_agg[(size_t)NMAX * HW];  // aggregation accumulator (re-init every call)

// ---------------------------------------------------------------------------
__global__ void k_init_deg(int n) {
    int i = blockIdx.x * blockDim.x + threadIdx.x;
    if (i < n) g_deg[i] = 1.0f;  // self-loop
}

__global__ void k_count_deg(const int* __restrict__ dst, int E) {
    int e = blockIdx.x * blockDim.x + threadIdx.x;
    if (e < E) atomicAdd(&g_deg[dst[e]], 1.0f);
}

__global__ void k_dinv(int n) {
    int i = blockIdx.x * blockDim.x + threadIdx.x;
    if (i < n) g_dinv[i] = rsqrtf(g_deg[i]);
}

// h = x @ W1 ; agg = h * dinv^2 (self-loop init). One warp per row.
__global__ void k_gemm1(const float* __restrict__ x, const float* __restrict__ W1, int n) {
    __shared__ float Ws[32 * 64];
    for (int i = threadIdx.x; i < 32 * 64; i += blockDim.x) Ws[i] = W1[i];
    __syncthreads();
    int warp = threadIdx.x >> 5, lane = threadIdx.x & 31;
    int r = blockIdx.x * 8 + warp;
    if (r >= n) return;
    float xv = x[(size_t)r * 32 + lane];
    float a0 = 0.f, a1 = 0.f;
#pragma unroll
    for (int k = 0; k < 32; k++) {
        float xk = __shfl_sync(0xffffffffu, xv, k);
        a0 = fmaf(xk, Ws[k * 64 + lane], a0);
        a1 = fmaf(xk, Ws[k * 64 + lane + 32], a1);
    }
    size_t base = (size_t)r * 64;
    float di = g_dinv[r], d2 = di * di;
    g_h[base + lane] = a0;
    g_h[base + lane + 32] = a1;
    g_agg[base + lane] = a0 * d2;
    g_agg[base + lane + 32] = a1 * d2;
}

// Edge scatter: agg[dst] += h[src] * dinv[src]*dinv[dst]. One warp per edge,
// each lane owns 2 contiguous floats (float2 gather, 2 RED.ADD.F32).
__global__ void k_edge(const int* __restrict__ src,
                       const int* __restrict__ dst, int E) {
    int e = blockIdx.x * 8 + (threadIdx.x >> 5);
    if (e >= E) return;
    int lane = threadIdx.x & 31;
    int s = src[e], d = dst[e];                // uniform per warp -> broadcast
    float coef = g_dinv[s] * g_dinv[d];
    const float2 v = *(const float2*)(g_h + (size_t)s * 64 + lane * 2);
    float* ap = g_agg + (size_t)d * 64 + lane * 2;
    atomicAdd(ap, v.x * coef);
    atomicAdd(ap + 1, v.y * coef);
}

// h2 = relu(agg + b1) @ W2 ; agg re-init (in-place, row-local) = h2 * dinv^2.
__global__ void k_gemm2(const float* __restrict__ W2, const float* __restrict__ b1, int n) {
    __shared__ float Ws[64 * 64];
    __shared__ float rowbuf[8][64];
    for (int i = threadIdx.x; i < 64 * 64; i += blockDim.x) Ws[i] = W2[i];
    __syncthreads();
    int warp = threadIdx.x >> 5, lane = threadIdx.x & 31;
    int r = blockIdx.x * 8 + warp;
    if (r >= n) return;
    size_t base = (size_t)r * 64;
    float2 av = *(const float2*)(g_agg + base + (size_t)lane * 2);
    rowbuf[warp][lane * 2]     = fmaxf(av.x + b1[lane * 2], 0.f);
    rowbuf[warp][lane * 2 + 1] = fmaxf(av.y + b1[lane * 2 + 1], 0.f);
    __syncwarp();
    float a0 = 0.f, a1 = 0.f;
#pragma unroll
    for (int k = 0; k < 64; k++) {
        float ak = rowbuf[warp][k];
        a0 = fmaf(ak, Ws[k * 64 + lane], a0);
        a1 = fmaf(ak, Ws[k * 64 + lane + 32], a1);
    }
    float di = g_dinv[r], d2 = di * di;
    g_h[base + lane] = a0;
    g_h[base + lane + 32] = a1;
    g_agg[base + lane] = a0 * d2;
    g_agg[base + lane + 32] = a1 * d2;
}

// out[g] = relu(agg[g,:] + b2_bcast) . Wfc + bfc.  One warp per graph (896 elems).
__global__ void k_final(const float* __restrict__ b2, const float* __restrict__ Wfc,
                        const float* __restrict__ bfc, float* __restrict__ out, int B) {
    __shared__ float Ws[896];
    __shared__ float bs[64];
    for (int i = threadIdx.x; i < 896; i += blockDim.x) Ws[i] = Wfc[i];
    if (threadIdx.x < 64) bs[threadIdx.x] = b2[threadIdx.x];
    __syncthreads();
    int warp = threadIdx.x >> 5, lane = threadIdx.x & 31;
    int g = blockIdx.x * 8 + warp;
    if (g >= B) return;
    const float* row = g_agg + (size_t)g * 896;
    float acc = 0.f;
#pragma unroll
    for (int j = 0; j < 7; j++) {
        int idx = (j * 32 + lane) * 4;
        float4 v = *(const float4*)(row + idx);
        acc = fmaf(fmaxf(v.x + bs[idx & 63], 0.f), Ws[idx], acc);
        acc = fmaf(fmaxf(v.y + bs[(idx + 1) & 63], 0.f), Ws[idx + 1], acc);
        acc = fmaf(fmaxf(v.z + bs[(idx + 2) & 63], 0.f), Ws[idx + 2], acc);
        acc = fmaf(fmaxf(v.w + bs[(idx + 3) & 63], 0.f), Ws[idx + 3], acc);
    }
#pragma unroll
    for (int o = 16; o; o >>= 1) acc += __shfl_down_sync(0xffffffffu, acc, o);
    if (lane == 0) out[g] = acc + bfc[0];
}

// ---------------------------------------------------------------------------
extern "C" void kernel_launch(void* const* d_in, const int* in_sizes, int n_in,
                              void* d_out, int out_size) {
    const float* x    = (const float*)d_in[0];
    const int*   edges = (const int*)d_in[1];   // int32: JAX x64 disabled downcasts int64
    const float* W1   = (const float*)d_in[2];
    const float* b1   = (const float*)d_in[3];
    const float* W2   = (const float*)d_in[4];
    const float* b2   = (const float*)d_in[5];
    const float* Wfc  = (const float*)d_in[6];
    const float* bfc  = (const float*)d_in[7];
    float* out = (float*)d_out;

    int n = in_sizes[0] / 32;   // 700000
    int E = in_sizes[1] / 2;    // 4000000
    int B = n / 14;             // 50000
    const int* src = edges;
    const int* dst = edges + E;

    k_init_deg<<<(n + 255) / 256, 256>>>(n);
    k_count_deg<<<(E + 255) / 256, 256>>>(dst, E);
    k_dinv<<<(n + 255) / 256, 256>>>(n);

    // Layer 1
    k_gemm1<<<(n + 7) / 8, 256>>>(x, W1, n);
    k_edge<<<(E + 7) / 8, 256>>>(src, dst, E);

    // Layer 2 (fused relu+bias+GEMM+self-loop re-init)
    k_gemm2<<<(n + 7) / 8, 256>>>(W2, b1, n);
    k_edge<<<(E + 7) / 8, 256>>>(src, dst, E);

    // FC head
    k_final<<<(B + 7) / 8, 256>>>(b2, Wfc, bfc, out, B);
}

// round 6
// speedup vs baseline: 1.7506x; 1.7482x over previous
#include <cuda_runtime.h>
#include <stdint.h>

#define NMAX 700000
#define EMAX 4000000
#define SCAN_B 1024
#define NBLK ((NMAX + SCAN_B - 1) / SCAN_B)   // 684

// Scratch (__device__ globals; allocation-free rule)
__device__ int   g_cnt[NMAX];        // in-degree (edges only)
__device__ int   g_rowptr[NMAX];     // CSR row start (exclusive prefix of cnt)
__device__ int   g_cursor[NMAX];
__device__ int   g_srcs[EMAX];       // CSR column (src) ids, grouped by dst
__device__ int   g_bsum[SCAN_B];
__device__ int   g_boff[SCAN_B];
__device__ float g_dinv[NMAX];
__device__ float g_h[(size_t)NMAX * 64];     // hs = h * dinv (layer 1 then layer 2)
__device__ float g_agg[(size_t)NMAX * 64];   // layer-1 aggregate (pre-bias)

// ---------------------------------------------------------------------------
__global__ void k_zero_cnt(int n) {
    int i = blockIdx.x * blockDim.x + threadIdx.x;
    if (i < n) g_cnt[i] = 0;
}

__global__ void k_cnt(const int* __restrict__ dst, int E) {
    int e = blockIdx.x * blockDim.x + threadIdx.x;
    if (e < E) atomicAdd(&g_cnt[dst[e]], 1);
}

__global__ void k_scan1(int n) {
    __shared__ int sh[SCAN_B];
    int i = blockIdx.x * SCAN_B + threadIdx.x;
    int v = (i < n) ? g_cnt[i] : 0;
    sh[threadIdx.x] = v;
    __syncthreads();
    for (int off = 1; off < SCAN_B; off <<= 1) {
        int t = (threadIdx.x >= off) ? sh[threadIdx.x - off] : 0;
        __syncthreads();
        sh[threadIdx.x] += t;
        __syncthreads();
    }
    if (i < n) g_rowptr[i] = sh[threadIdx.x] - v;  // exclusive
    if (threadIdx.x == SCAN_B - 1) g_bsum[blockIdx.x] = sh[SCAN_B - 1];
}

__global__ void k_scan2(int nb) {
    __shared__ int sh[SCAN_B];
    int v = (threadIdx.x < nb) ? g_bsum[threadIdx.x] : 0;
    sh[threadIdx.x] = v;
    __syncthreads();
    for (int off = 1; off < SCAN_B; off <<= 1) {
        int t = (threadIdx.x >= off) ? sh[threadIdx.x - off] : 0;
        __syncthreads();
        sh[threadIdx.x] += t;
        __syncthreads();
    }
    if (threadIdx.x < nb) g_boff[threadIdx.x] = sh[threadIdx.x] - v;  // exclusive
}

// finalize rowptr, zero fill cursors, compute dinv = rsqrt(deg+1)
__global__ void k_scan3(int n) {
    int i = blockIdx.x * blockDim.x + threadIdx.x;
    if (i < n) {
        g_rowptr[i] += g_boff[i / SCAN_B];
        g_cursor[i] = 0;
        g_dinv[i] = rsqrtf((float)(g_cnt[i] + 1));
    }
}

__global__ void k_fill(const int* __restrict__ src, const int* __restrict__ dst, int E) {
    int e = blockIdx.x * blockDim.x + threadIdx.x;
    if (e < E) {
        int d = dst[e];
        int pos = atomicAdd(&g_cursor[d], 1);
        g_srcs[g_rowptr[d] + pos] = src[e];
    }
}

// ---------------------------------------------------------------------------
// hs1 = (x @ W1) * dinv.  4 rows per warp (amortized W LDS).
__global__ void k_gemm1(const float* __restrict__ x, const float* __restrict__ W1, int n) {
    __shared__ float Ws[32 * 64];
    for (int i = threadIdx.x; i < 32 * 64; i += blockDim.x) Ws[i] = W1[i];
    __syncthreads();
    int warp = threadIdx.x >> 5, lane = threadIdx.x & 31;
    int r0 = (blockIdx.x * 8 + warp) * 4;
    if (r0 >= n) return;
    float xv[4];
#pragma unroll
    for (int j = 0; j < 4; j++)
        xv[j] = (r0 + j < n) ? x[(size_t)(r0 + j) * 32 + lane] : 0.f;
    float a0[4] = {0, 0, 0, 0}, a1[4] = {0, 0, 0, 0};
#pragma unroll
    for (int k = 0; k < 32; k++) {
        float w0 = Ws[k * 64 + lane], w1 = Ws[k * 64 + lane + 32];
#pragma unroll
        for (int j = 0; j < 4; j++) {
            float xk = __shfl_sync(0xffffffffu, xv[j], k);
            a0[j] = fmaf(xk, w0, a0[j]);
            a1[j] = fmaf(xk, w1, a1[j]);
        }
    }
#pragma unroll
    for (int j = 0; j < 4; j++) {
        int r = r0 + j;
        if (r < n) {
            float di = g_dinv[r];
            size_t base = (size_t)r * 64;
            g_h[base + lane]      = a0[j] * di;
            g_h[base + lane + 32] = a1[j] * di;
        }
    }
}

// agg[d] = dinv[d] * (hs[d] + sum_{s in N(d)} hs[s]).  Warp per node.
__global__ void k_gather1(int n) {
    int warp = threadIdx.x >> 5, lane = threadIdx.x & 31;
    int d = blockIdx.x * 8 + warp;
    if (d >= n) return;
    int start = g_rowptr[d], len = g_cnt[d];
    size_t base = (size_t)d * 64;
    float2 acc = *(const float2*)(g_h + base + (size_t)lane * 2);  // self-loop (hs[d])
    for (int j0 = 0; j0 < len; j0 += 32) {
        int m = min(32, len - j0);
        int sidx = (lane < m) ? g_srcs[start + j0 + lane] : 0;
        int j = 0;
        for (; j + 4 <= m; j += 4) {
            int s0 = __shfl_sync(0xffffffffu, sidx, j);
            int s1 = __shfl_sync(0xffffffffu, sidx, j + 1);
            int s2 = __shfl_sync(0xffffffffu, sidx, j + 2);
            int s3 = __shfl_sync(0xffffffffu, sidx, j + 3);
            float2 v0 = *(const float2*)(g_h + (size_t)s0 * 64 + (size_t)lane * 2);
            float2 v1 = *(const float2*)(g_h + (size_t)s1 * 64 + (size_t)lane * 2);
            float2 v2 = *(const float2*)(g_h + (size_t)s2 * 64 + (size_t)lane * 2);
            float2 v3 = *(const float2*)(g_h + (size_t)s3 * 64 + (size_t)lane * 2);
            acc.x += v0.x + v1.x + v2.x + v3.x;
            acc.y += v0.y + v1.y + v2.y + v3.y;
        }
        for (; j < m; j++) {
            int s = __shfl_sync(0xffffffffu, sidx, j);
            float2 v = *(const float2*)(g_h + (size_t)s * 64 + (size_t)lane * 2);
            acc.x += v.x;
            acc.y += v.y;
        }
    }
    float di = g_dinv[d];
    float2 o;
    o.x = acc.x * di;
    o.y = acc.y * di;
    *(float2*)(g_agg + base + (size_t)lane * 2) = o;
}

// hs2 = (relu(agg + b1) @ W2) * dinv.  4 rows per warp, shfl broadcast of t.
__global__ void k_gemm2(const float* __restrict__ W2, const float* __restrict__ b1, int n) {
    __shared__ float Ws[64 * 64];
    for (int i = threadIdx.x; i < 64 * 64; i += blockDim.x) Ws[i] = W2[i];
    __syncthreads();
    int warp = threadIdx.x >> 5, lane = threadIdx.x & 31;
    int r0 = (blockIdx.x * 8 + warp) * 4;
    if (r0 >= n) return;
    float bx = b1[lane * 2], by = b1[lane * 2 + 1];
    float2 t[4];
#pragma unroll
    for (int j = 0; j < 4; j++) {
        if (r0 + j < n) {
            float2 av = *(const float2*)(g_agg + (size_t)(r0 + j) * 64 + (size_t)lane * 2);
            t[j].x = fmaxf(av.x + bx, 0.f);
            t[j].y = fmaxf(av.y + by, 0.f);
        } else {
            t[j].x = 0.f;
            t[j].y = 0.f;
        }
    }
    float a0[4] = {0, 0, 0, 0}, a1[4] = {0, 0, 0, 0};
#pragma unroll
    for (int k = 0; k < 64; k++) {
        float w0 = Ws[k * 64 + lane], w1 = Ws[k * 64 + lane + 32];
#pragma unroll
        for (int j = 0; j < 4; j++) {
            float tk = __shfl_sync(0xffffffffu, (k & 1) ? t[j].y : t[j].x, k >> 1);
            a0[j] = fmaf(tk, w0, a0[j]);
            a1[j] = fmaf(tk, w1, a1[j]);
        }
    }
#pragma unroll
    for (int j = 0; j < 4; j++) {
        int r = r0 + j;
        if (r < n) {
            float di = g_dinv[r];
            size_t base = (size_t)r * 64;
            g_h[base + lane]      = a0[j] * di;
            g_h[base + lane + 32] = a1[j] * di;
        }
    }
}

__global__ void k_out_init(const float* __restrict__ bfc, float* __restrict__ out, int B) {
    int g = blockIdx.x * blockDim.x + threadIdx.x;
    if (g < B) out[g] = bfc[0];
}

// Layer-2 gather fused with relu+b2 and FC head.
// per node d: t = relu(dinv[d]*(hs2[d]+sum hs2[src]) + b2);
//             out[d/14] += t . Wfc[(d%14)*64 : +64]
__global__ void k_gather2_fc(const float* __restrict__ b2, const float* __restrict__ Wfc,
                             float* __restrict__ out, int n) {
    int warp = threadIdx.x >> 5, lane = threadIdx.x & 31;
    int d = blockIdx.x * 8 + warp;
    if (d >= n) return;
    int start = g_rowptr[d], len = g_cnt[d];
    size_t base = (size_t)d * 64;
    float2 acc = *(const float2*)(g_h + base + (size_t)lane * 2);
    for (int j0 = 0; j0 < len; j0 += 32) {
        int m = min(32, len - j0);
        int sidx = (lane < m) ? g_srcs[start + j0 + lane] : 0;
        int j = 0;
        for (; j + 4 <= m; j += 4) {
            int s0 = __shfl_sync(0xffffffffu, sidx, j);
            int s1 = __shfl_sync(0xffffffffu, sidx, j + 1);
            int s2 = __shfl_sync(0xffffffffu, sidx, j + 2);
            int s3 = __shfl_sync(0xffffffffu, sidx, j + 3);
            float2 v0 = *(const float2*)(g_h + (size_t)s0 * 64 + (size_t)lane * 2);
            float2 v1 = *(const float2*)(g_h + (size_t)s1 * 64 + (size_t)lane * 2);
            float2 v2 = *(const float2*)(g_h + (size_t)s2 * 64 + (size_t)lane * 2);
            float2 v3 = *(const float2*)(g_h + (size_t)s3 * 64 + (size_t)lane * 2);
            acc.x += v0.x + v1.x + v2.x + v3.x;
            acc.y += v0.y + v1.y + v2.y + v3.y;
        }
        for (; j < m; j++) {
            int s = __shfl_sync(0xffffffffu, sidx, j);
            float2 v = *(const float2*)(g_h + (size_t)s * 64 + (size_t)lane * 2);
            acc.x += v.x;
            acc.y += v.y;
        }
    }
    float di = g_dinv[d];
    float t0 = fmaxf(acc.x * di + b2[lane * 2], 0.f);
    float t1 = fmaxf(acc.y * di + b2[lane * 2 + 1], 0.f);
    int pos = d % 14, graph = d / 14;
    float p = t0 * Wfc[pos * 64 + lane * 2] + t1 * Wfc[pos * 64 + lane * 2 + 1];
#pragma unroll
    for (int o = 16; o; o >>= 1) p += __shfl_down_sync(0xffffffffu, p, o);
    if (lane == 0) atomicAdd(&out[graph], p);
}

// ---------------------------------------------------------------------------
extern "C" void kernel_launch(void* const* d_in, const int* in_sizes, int n_in,
                              void* d_out, int out_size) {
    const float* x     = (const float*)d_in[0];
    const int*   edges = (const int*)d_in[1];   // int32 (JAX x64 disabled)
    const float* W1    = (const float*)d_in[2];
    const float* b1    = (const float*)d_in[3];
    const float* W2    = (const float*)d_in[4];
    const float* b2    = (const float*)d_in[5];
    const float* Wfc   = (const float*)d_in[6];
    const float* bfc   = (const float*)d_in[7];
    float* out = (float*)d_out;

    int n = in_sizes[0] / 32;   // 700000
    int E = in_sizes[1] / 2;    // 4000000
    int B = n / 14;             // 50000
    const int* src = edges;
    const int* dst = edges + E;

    int nb = (n + SCAN_B - 1) / SCAN_B;

    // CSR build (dst-grouped) + dinv
    k_zero_cnt<<<(n + 255) / 256, 256>>>(n);
    k_cnt<<<(E + 255) / 256, 256>>>(dst, E);
    k_scan1<<<nb, SCAN_B>>>(n);
    k_scan2<<<1, SCAN_B>>>(nb);
    k_scan3<<<(n + 255) / 256, 256>>>(n);
    k_fill<<<(E + 255) / 256, 256>>>(src, dst, E);

    // Layer 1
    k_gemm1<<<(n + 31) / 32, 256>>>(x, W1, n);
    k_gather1<<<(n + 7) / 8, 256>>>(n);

    // Layer 2
    k_gemm2<<<(n + 31) / 32, 256>>>(W2, b1, n);

    // FC head fused into layer-2 gather
    k_out_init<<<(B + 255) / 256, 256>>>(bfc, out, B);
    k_gather2_fc<<<(n + 7) / 8, 256>>>(b2, Wfc, out, n);
}

// round 7
// speedup vs baseline: 2.1855x; 1.2484x over previous
#include <cuda_runtime.h>
#include <cuda_fp16.h>
#include <stdint.h>

#define NMAX 700000
#define EMAX 4000000
#define SCAN_B 1024

// Scratch (__device__ globals; allocation-free rule)
__device__ int     g_cnt[NMAX];        // in-degree (edges only)
__device__ int     g_rowptr[NMAX];     // CSR row start (exclusive prefix of cnt)
__device__ int     g_cursor[NMAX];
__device__ int     g_srcs[EMAX];       // CSR column (src) ids, grouped by dst
__device__ int     g_bsum[SCAN_B];
__device__ int     g_boff[SCAN_B];
__device__ float   g_dinv[NMAX];
__device__ __half2 g_h[(size_t)NMAX * 32];   // hs = h * dinv, half2-packed (feat 2l,2l+1)
__device__ float   g_agg[(size_t)NMAX * 64]; // layer-1 aggregate (pre-bias), fp32

// ---------------------------------------------------------------------------
__global__ void k_zero_cnt(int n) {
    int i = blockIdx.x * blockDim.x + threadIdx.x;
    if (i < n) g_cnt[i] = 0;
}

__global__ void k_cnt(const int* __restrict__ dst, int E) {
    int e = blockIdx.x * blockDim.x + threadIdx.x;
    if (e < E) atomicAdd(&g_cnt[dst[e]], 1);
}

__global__ void k_scan1(int n) {
    __shared__ int sh[SCAN_B];
    int i = blockIdx.x * SCAN_B + threadIdx.x;
    int v = (i < n) ? g_cnt[i] : 0;
    sh[threadIdx.x] = v;
    __syncthreads();
    for (int off = 1; off < SCAN_B; off <<= 1) {
        int t = (threadIdx.x >= off) ? sh[threadIdx.x - off] : 0;
        __syncthreads();
        sh[threadIdx.x] += t;
        __syncthreads();
    }
    if (i < n) g_rowptr[i] = sh[threadIdx.x] - v;  // exclusive
    if (threadIdx.x == SCAN_B - 1) g_bsum[blockIdx.x] = sh[SCAN_B - 1];
}

__global__ void k_scan2(int nb) {
    __shared__ int sh[SCAN_B];
    int v = (threadIdx.x < nb) ? g_bsum[threadIdx.x] : 0;
    sh[threadIdx.x] = v;
    __syncthreads();
    for (int off = 1; off < SCAN_B; off <<= 1) {
        int t = (threadIdx.x >= off) ? sh[threadIdx.x - off] : 0;
        __syncthreads();
        sh[threadIdx.x] += t;
        __syncthreads();
    }
    if (threadIdx.x < nb) g_boff[threadIdx.x] = sh[threadIdx.x] - v;  // exclusive
}

// finalize rowptr, zero fill cursors, compute dinv = rsqrt(deg+1)
__global__ void k_scan3(int n) {
    int i = blockIdx.x * blockDim.x + threadIdx.x;
    if (i < n) {
        g_rowptr[i] += g_boff[i / SCAN_B];
        g_cursor[i] = 0;
        g_dinv[i] = rsqrtf((float)(g_cnt[i] + 1));
    }
}

__global__ void k_fill(const int* __restrict__ src, const int* __restrict__ dst, int E) {
    int e = blockIdx.x * blockDim.x + threadIdx.x;
    if (e < E) {
        int d = dst[e];
        int pos = atomicAdd(&g_cursor[d], 1);
        g_srcs[g_rowptr[d] + pos] = src[e];
    }
}

// ---------------------------------------------------------------------------
// hs1 = (x @ W1) * dinv, stored half2. Lane l owns features (2l, 2l+1).
__global__ void k_gemm1(const float* __restrict__ x, const float* __restrict__ W1, int n) {
    __shared__ float2 Ws[32 * 32];   // Ws[k*32+j] = (W1[k][2j], W1[k][2j+1])
    for (int i = threadIdx.x; i < 32 * 64; i += blockDim.x)
        ((float*)Ws)[i] = W1[i];
    __syncthreads();
    int warp = threadIdx.x >> 5, lane = threadIdx.x & 31;
    int r0 = (blockIdx.x * 8 + warp) * 4;
    if (r0 >= n) return;
    float xv[4];
#pragma unroll
    for (int j = 0; j < 4; j++)
        xv[j] = (r0 + j < n) ? x[(size_t)(r0 + j) * 32 + lane] : 0.f;
    float a0[4] = {0, 0, 0, 0}, a1[4] = {0, 0, 0, 0};
#pragma unroll
    for (int k = 0; k < 32; k++) {
        float2 w = Ws[k * 32 + lane];
#pragma unroll
        for (int j = 0; j < 4; j++) {
            float xk = __shfl_sync(0xffffffffu, xv[j], k);
            a0[j] = fmaf(xk, w.x, a0[j]);
            a1[j] = fmaf(xk, w.y, a1[j]);
        }
    }
#pragma unroll
    for (int j = 0; j < 4; j++) {
        int r = r0 + j;
        if (r < n) {
            float di = g_dinv[r];
            g_h[(size_t)r * 32 + lane] = __floats2half2_rn(a0[j] * di, a1[j] * di);
        }
    }
}

// agg[d] = dinv[d] * (hs[d] + sum_{s in N(d)} hs[s]).  Warp per node, half2 gather.
__global__ void k_gather1(int n) {
    int warp = threadIdx.x >> 5, lane = threadIdx.x & 31;
    int d = blockIdx.x * 8 + warp;
    if (d >= n) return;
    int start = g_rowptr[d], len = g_cnt[d];
    float2 acc = __half22float2(__ldg(&g_h[(size_t)d * 32 + lane]));  // self-loop
    for (int j0 = 0; j0 < len; j0 += 32) {
        int m = min(32, len - j0);
        int sidx = (lane < m) ? g_srcs[start + j0 + lane] : 0;
        int j = 0;
        for (; j + 4 <= m; j += 4) {
            int s0 = __shfl_sync(0xffffffffu, sidx, j);
            int s1 = __shfl_sync(0xffffffffu, sidx, j + 1);
            int s2 = __shfl_sync(0xffffffffu, sidx, j + 2);
            int s3 = __shfl_sync(0xffffffffu, sidx, j + 3);
            float2 v0 = __half22float2(__ldg(&g_h[(size_t)s0 * 32 + lane]));
            float2 v1 = __half22float2(__ldg(&g_h[(size_t)s1 * 32 + lane]));
            float2 v2 = __half22float2(__ldg(&g_h[(size_t)s2 * 32 + lane]));
            float2 v3 = __half22float2(__ldg(&g_h[(size_t)s3 * 32 + lane]));
            acc.x += v0.x + v1.x + v2.x + v3.x;
            acc.y += v0.y + v1.y + v2.y + v3.y;
        }
        for (; j < m; j++) {
            int s = __shfl_sync(0xffffffffu, sidx, j);
            float2 v = __half22float2(__ldg(&g_h[(size_t)s * 32 + lane]));
            acc.x += v.x;
            acc.y += v.y;
        }
    }
    float di = g_dinv[d];
    float2 o;
    o.x = acc.x * di;
    o.y = acc.y * di;
    *(float2*)(g_agg + (size_t)d * 64 + (size_t)lane * 2) = o;
}

// hs2 = (relu(agg + b1) @ W2) * dinv, stored half2.  4 rows per warp.
__global__ void k_gemm2(const float* __restrict__ W2, const float* __restrict__ b1, int n) {
    __shared__ float2 Ws[64 * 32];   // Ws[k*32+j] = (W2[k][2j], W2[k][2j+1])
    for (int i = threadIdx.x; i < 64 * 64; i += blockDim.x)
        ((float*)Ws)[i] = W2[i];
    __syncthreads();
    int warp = threadIdx.x >> 5, lane = threadIdx.x & 31;
    int r0 = (blockIdx.x * 8 + warp) * 4;
    if (r0 >= n) return;
    float bx = b1[lane * 2], by = b1[lane * 2 + 1];
    float2 t[4];
#pragma unroll
    for (int j = 0; j < 4; j++) {
        if (r0 + j < n) {
            float2 av = *(const float2*)(g_agg + (size_t)(r0 + j) * 64 + (size_t)lane * 2);
            t[j].x = fmaxf(av.x + bx, 0.f);
            t[j].y = fmaxf(av.y + by, 0.f);
        } else {
            t[j].x = 0.f;
            t[j].y = 0.f;
        }
    }
    float a0[4] = {0, 0, 0, 0}, a1[4] = {0, 0, 0, 0};
#pragma unroll
    for (int k = 0; k < 64; k++) {
        float2 w = Ws[k * 32 + lane];
#pragma unroll
        for (int j = 0; j < 4; j++) {
            float tk = __shfl_sync(0xffffffffu, (k & 1) ? t[j].y : t[j].x, k >> 1);
            a0[j] = fmaf(tk, w.x, a0[j]);
            a1[j] = fmaf(tk, w.y, a1[j]);
        }
    }
#pragma unroll
    for (int j = 0; j < 4; j++) {
        int r = r0 + j;
        if (r < n) {
            float di = g_dinv[r];
            g_h[(size_t)r * 32 + lane] = __floats2half2_rn(a0[j] * di, a1[j] * di);
        }
    }
}

__global__ void k_out_init(const float* __restrict__ bfc, float* __restrict__ out, int B) {
    int g = blockIdx.x * blockDim.x + threadIdx.x;
    if (g < B) out[g] = bfc[0];
}

// Layer-2 gather fused with relu+b2 and FC head.
__global__ void k_gather2_fc(const float* __restrict__ b2, const float* __restrict__ Wfc,
                             float* __restrict__ out, int n) {
    int warp = threadIdx.x >> 5, lane = threadIdx.x & 31;
    int d = blockIdx.x * 8 + warp;
    if (d >= n) return;
    int start = g_rowptr[d], len = g_cnt[d];
    float2 acc = __half22float2(__ldg(&g_h[(size_t)d * 32 + lane]));
    for (int j0 = 0; j0 < len; j0 += 32) {
        int m = min(32, len - j0);
        int sidx = (lane < m) ? g_srcs[start + j0 + lane] : 0;
        int j = 0;
        for (; j + 4 <= m; j += 4) {
            int s0 = __shfl_sync(0xffffffffu, sidx, j);
            int s1 = __shfl_sync(0xffffffffu, sidx, j + 1);
            int s2 = __shfl_sync(0xffffffffu, sidx, j + 2);
            int s3 = __shfl_sync(0xffffffffu, sidx, j + 3);
            float2 v0 = __half22float2(__ldg(&g_h[(size_t)s0 * 32 + lane]));
            float2 v1 = __half22float2(__ldg(&g_h[(size_t)s1 * 32 + lane]));
            float2 v2 = __half22float2(__ldg(&g_h[(size_t)s2 * 32 + lane]));
            float2 v3 = __half22float2(__ldg(&g_h[(size_t)s3 * 32 + lane]));
            acc.x += v0.x + v1.x + v2.x + v3.x;
            acc.y += v0.y + v1.y + v2.y + v3.y;
        }
        for (; j < m; j++) {
            int s = __shfl_sync(0xffffffffu, sidx, j);
            float2 v = __half22float2(__ldg(&g_h[(size_t)s * 32 + lane]));
            acc.x += v.x;
            acc.y += v.y;
        }
    }
    float di = g_dinv[d];
    float t0 = fmaxf(acc.x * di + b2[lane * 2], 0.f);
    float t1 = fmaxf(acc.y * di + b2[lane * 2 + 1], 0.f);
    int pos = d % 14, graph = d / 14;
    float p = t0 * Wfc[pos * 64 + lane * 2] + t1 * Wfc[pos * 64 + lane * 2 + 1];
#pragma unroll
    for (int o = 16; o; o >>= 1) p += __shfl_down_sync(0xffffffffu, p, o);
    if (lane == 0) atomicAdd(&out[graph], p);
}

// ---------------------------------------------------------------------------
extern "C" void kernel_launch(void* const* d_in, const int* in_sizes, int n_in,
                              void* d_out, int out_size) {
    const float* x     = (const float*)d_in[0];
    const int*   edges = (const int*)d_in[1];   // int32 (JAX x64 disabled)
    const float* W1    = (const float*)d_in[2];
    const float* b1    = (const float*)d_in[3];
    const float* W2    = (const float*)d_in[4];
    const float* b2    = (const float*)d_in[5];
    const float* Wfc   = (const float*)d_in[6];
    const float* bfc   = (const float*)d_in[7];
    float* out = (float*)d_out;

    int n = in_sizes[0] / 32;   // 700000
    int E = in_sizes[1] / 2;    // 4000000
    int B = n / 14;             // 50000
    const int* src = edges;
    const int* dst = edges + E;

    int nb = (n + SCAN_B - 1) / SCAN_B;

    // CSR build (dst-grouped) + dinv
    k_zero_cnt<<<(n + 255) / 256, 256>>>(n);
    k_cnt<<<(E + 255) / 256, 256>>>(dst, E);
    k_scan1<<<nb, SCAN_B>>>(n);
    k_scan2<<<1, SCAN_B>>>(nb);
    k_scan3<<<(n + 255) / 256, 256>>>(n);
    k_fill<<<(E + 255) / 256, 256>>>(src, dst, E);

    // Layer 1
    k_gemm1<<<(n + 31) / 32, 256>>>(x, W1, n);
    k_gather1<<<(n + 7) / 8, 256>>>(n);

    // Layer 2
    k_gemm2<<<(n + 31) / 32, 256>>>(W2, b1, n);

    // FC head fused into layer-2 gather
    k_out_init<<<(B + 255) / 256, 256>>>(bfc, out, B);
    k_gather2_fc<<<(n + 7) / 8, 256>>>(b2, Wfc, out, n);
}